// round 2
// baseline (speedup 1.0000x reference)
#include <cuda_runtime.h>
#include <cstdint>
#include <cstddef>

// Problem constants
#define B_   1024
#define S_   200
#define D_   64
#define NI_  4
#define SP   66          // padded smem row stride (words); 8B-aligned, conflict-free for v2 loads
#define JPAD 224         // padded j extent for adj (7 * 32)

// Scratch (device globals: allocation-free rule)
__device__ float g_up[B_ * D_];                               // user profile      0.25 MB
__device__ float g_item[(size_t)B_ * S_ * D_];                // item_his          52.4 MB
__device__ float g_hat[(size_t)B_ * NI_ * S_ * D_];           // hat (B,NI,S,D)    209.7 MB

// ---- packed f32x2 helpers (sm_100+): FFMA2 at 2x 3-reg FFMA rate ----
__device__ __forceinline__ unsigned long long ld2(const float* p) {
    return *reinterpret_cast<const unsigned long long*>(p);
}
__device__ __forceinline__ void fma2(unsigned long long& d,
                                     unsigned long long a,
                                     unsigned long long b) {
    asm("fma.rn.f32x2 %0, %1, %2, %3;" : "=l"(d) : "l"(a), "l"(b), "l"(d));
}
__device__ __forceinline__ float sum2(unsigned long long v) {
    float lo = __int_as_float((int)(v & 0xffffffffULL));
    float hi = __int_as_float((int)(v >> 32));
    return lo + hi;
}

// ============================================================
// K1a: user_profile = 0.25*(U[uid] + G[gender] + A[age] + O[occup])
// ============================================================
__global__ void up_kernel(const int* __restrict__ uid, const int* __restrict__ age,
                          const int* __restrict__ gender, const int* __restrict__ occup,
                          const float* __restrict__ uet, const float* __restrict__ aget,
                          const float* __restrict__ gent, const float* __restrict__ occt) {
    int t = blockIdx.x * blockDim.x + threadIdx.x;   // B*D threads
    if (t >= B_ * D_) return;
    int b = t >> 6, d = t & 63;
    float v = uet[(size_t)uid[b] * D_ + d]
            + gent[(size_t)gender[b] * D_ + d]
            + aget[(size_t)age[b] * D_ + d]
            + occt[(size_t)occup[b] * D_ + d];
    g_up[t] = 0.25f * v;
}

// ============================================================
// K1b: item_his[b,s,:] = mid_emb[mid_his[b,s],:] * mask[b,s]   (float4)
// ============================================================
__global__ void item_kernel(const int* __restrict__ mid_his, const float* __restrict__ mask,
                            const float* __restrict__ mid_emb) {
    int i = blockIdx.x * blockDim.x + threadIdx.x;   // B*S*16 float4 slots
    if (i >= B_ * S_ * (D_ / 4)) return;
    int bs = i >> 4;            // (b,s) flat
    int d4 = i & 15;            // which float4 in the row
    float m = mask[bs];
    int idx = mid_his[bs];
    float4 v = reinterpret_cast<const float4*>(mid_emb)[(size_t)idx * 16 + d4];
    v.x *= m; v.y *= m; v.z *= m; v.w *= m;
    reinterpret_cast<float4*>(g_item)[i] = v;
}

// ============================================================
// K2: adj[b,i,j] = sigmoid(hu[b,i]·item[b,j]) * mask_i * mask_j
// one block per b; smem holds item/hu rows padded to JPAD
// ============================================================
#define ADJ_SMEM ((2 * JPAD * SP + JPAD + D_) * 4)
__global__ void __launch_bounds__(256, 1)
adj_kernel(const float* __restrict__ mask, float* __restrict__ out_adj) {
    extern __shared__ float sm[];
    float* sh_item = sm;                     // [JPAD][SP]
    float* sh_hu   = sm + JPAD * SP;         // [JPAD][SP]
    float* sh_mask = sh_hu + JPAD * SP;      // [JPAD]
    float* sh_up   = sh_mask + JPAD;         // [D]

    int b = blockIdx.x;
    int tid = threadIdx.x;

    if (tid < D_) sh_up[tid] = g_up[b * D_ + tid];
    for (int s = tid; s < JPAD; s += 256)
        sh_mask[s] = (s < S_) ? mask[b * S_ + s] : 0.f;
    __syncthreads();

    for (int f = tid; f < JPAD * D_; f += 256) {
        int s = f >> 6, d = f & 63;
        float v = (s < S_) ? g_item[((size_t)b * S_ + s) * D_ + d] : 0.f;
        sh_item[s * SP + d] = v;
        sh_hu[s * SP + d]   = v * sh_up[d];
    }
    __syncthreads();

    int tx = tid & 31, wid = tid >> 5;

    for (int ig = wid; ig < 25; ig += 8) {       // 25 groups of 8 i-rows
        int i0 = ig * 8;
        unsigned long long acc[8][7];
        #pragma unroll
        for (int r = 0; r < 8; r++)
            #pragma unroll
            for (int c = 0; c < 7; c++) acc[r][c] = 0ULL;

        #pragma unroll 4
        for (int dd = 0; dd < D_; dd += 2) {
            unsigned long long a2[8], b2[7];
            #pragma unroll
            for (int r = 0; r < 8; r++) a2[r] = ld2(&sh_hu[(i0 + r) * SP + dd]);
            #pragma unroll
            for (int c = 0; c < 7; c++) b2[c] = ld2(&sh_item[(tx + 32 * c) * SP + dd]);
            #pragma unroll
            for (int r = 0; r < 8; r++)
                #pragma unroll
                for (int c = 0; c < 7; c++) fma2(acc[r][c], a2[r], b2[c]);
        }

        #pragma unroll
        for (int r = 0; r < 8; r++) {
            float mi = sh_mask[i0 + r];
            #pragma unroll
            for (int c = 0; c < 7; c++) {
                int j = tx + 32 * c;
                if (j < S_) {
                    float x = sum2(acc[r][c]);
                    float sg = 1.f / (1.f + __expf(-x));
                    out_adj[((size_t)b * S_ + (i0 + r)) * S_ + j] = sg * mi * sh_mask[j];
                }
            }
        }
    }
}

// ============================================================
// K3: hat[b,s,e] = item[b,s,:]·w_capsule[s,e,:]; write as (B,NI,S,D)
// block = (s, b-tile of 64)
// ============================================================
#define HAT_SMEM (((NI_ * D_) * SP + 64 * SP) * 4)
__global__ void __launch_bounds__(256, 1)
hat_kernel(const float* __restrict__ wcap) {
    extern __shared__ float sm[];
    float* sh_w  = sm;                  // [256][SP]
    float* sh_it = sm + 256 * SP;       // [64][SP]

    int s  = blockIdx.x;
    int b0 = blockIdx.y * 64;
    int tid = threadIdx.x;

    const float* wsrc = wcap + (size_t)s * 256 * D_;
    for (int f = tid; f < 256 * D_; f += 256) {
        int e = f >> 6, d = f & 63;
        sh_w[e * SP + d] = wsrc[f];
    }
    for (int f = tid; f < 64 * D_; f += 256) {
        int r = f >> 6, d = f & 63;
        sh_it[r * SP + d] = g_item[(((size_t)(b0 + r)) * S_ + s) * D_ + d];
    }
    __syncthreads();

    int tx = tid & 31, ty = tid >> 5;
    unsigned long long acc[8][8];
    #pragma unroll
    for (int r = 0; r < 8; r++)
        #pragma unroll
        for (int c = 0; c < 8; c++) acc[r][c] = 0ULL;

    #pragma unroll 2
    for (int dd = 0; dd < D_; dd += 2) {
        unsigned long long a2[8], b2[8];
        #pragma unroll
        for (int r = 0; r < 8; r++) a2[r] = ld2(&sh_it[(ty * 8 + r) * SP + dd]);
        #pragma unroll
        for (int c = 0; c < 8; c++) b2[c] = ld2(&sh_w[(tx + 32 * c) * SP + dd]);
        #pragma unroll
        for (int r = 0; r < 8; r++)
            #pragma unroll
            for (int c = 0; c < 8; c++) fma2(acc[r][c], a2[r], b2[c]);
    }

    #pragma unroll
    for (int r = 0; r < 8; r++) {
        int b = b0 + ty * 8 + r;
        #pragma unroll
        for (int c = 0; c < 8; c++) {
            int e = tx + 32 * c;
            int k = e >> 6, d = e & 63;
            g_hat[(((size_t)b * NI_ + k) * S_ + s) * D_ + d] = sum2(acc[r][c]);
        }
    }
}

// ============================================================
// K4: dynamic routing (3 iters), block per b, hat[b] cached in smem
// ============================================================
#define RT_HAT  (NI_ * S_ * SP)                 // 52800 floats
#define RT_SMEM ((RT_HAT + 800 + 800 + S_ + 256 + 8) * 4)
__global__ void __launch_bounds__(256, 1)
route_kernel(const float* __restrict__ mask, float* __restrict__ out_cap) {
    extern __shared__ float sm[];
    float* sh_hat  = sm;                    // [NI][S][SP]
    float* sh_cw   = sh_hat + RT_HAT;       // [NI][S]
    float* sh_sw   = sh_cw + 800;           // [NI][S]
    float* sh_mask = sh_sw + 800;           // [S]
    float* sh_cap  = sh_mask + S_;          // [NI][D]
    float* sh_red  = sh_cap + 256;          // [8]

    int b = blockIdx.x, tid = threadIdx.x;
    const float* src = g_hat + (size_t)b * NI_ * S_ * D_;

    // load hat[b] (float4 global) into padded smem
    for (int f = tid; f < NI_ * S_ * (D_ / 4); f += 256) {
        int flat = f * 4;
        int ks = flat >> 6;       // k*S + s
        int d  = flat & 63;
        float4 v = reinterpret_cast<const float4*>(src)[f];
        float* dst = &sh_hat[ks * SP + d];
        dst[0] = v.x; dst[1] = v.y; dst[2] = v.z; dst[3] = v.w;
    }
    for (int f = tid; f < 800; f += 256) sh_cw[f] = 0.f;
    if (tid < S_) sh_mask[tid] = mask[b * S_ + tid];
    __syncthreads();

    int k = tid >> 6, d = tid & 63;       // 256 threads = NI*D exactly
    int lane = tid & 31, wid = tid >> 5;

    for (int it = 0; it < 3; it++) {
        // softmax over k at s = tid, then mask
        if (tid < S_) {
            float c0 = sh_cw[tid], c1 = sh_cw[200 + tid],
                  c2 = sh_cw[400 + tid], c3 = sh_cw[600 + tid];
            float m = fmaxf(fmaxf(c0, c1), fmaxf(c2, c3));
            float e0 = __expf(c0 - m), e1 = __expf(c1 - m),
                  e2 = __expf(c2 - m), e3 = __expf(c3 - m);
            float inv = 1.f / (e0 + e1 + e2 + e3);
            float z = (sh_mask[tid] == 0.f) ? 0.f : inv;
            sh_sw[tid]       = e0 * z;
            sh_sw[200 + tid] = e1 * z;
            sh_sw[400 + tid] = e2 * z;
            sh_sw[600 + tid] = e3 * z;
        }
        __syncthreads();

        // cap[k,d] = sum_s sw[k,s] * hat[k,s,d]
        float acc = 0.f;
        {
            const float* hb  = &sh_hat[k * S_ * SP + d];
            const float* swb = &sh_sw[k * S_];
            #pragma unroll 4
            for (int s2 = 0; s2 < S_; s2++) acc += swb[s2] * hb[s2 * SP];
        }
        // squash: n = ||cap_k||^2 across d (2 warps per k)
        float nsq = acc * acc;
        #pragma unroll
        for (int off = 16; off > 0; off >>= 1)
            nsq += __shfl_xor_sync(0xffffffffu, nsq, off);
        if (lane == 0) sh_red[wid] = nsq;
        __syncthreads();
        float n = sh_red[2 * k] + sh_red[2 * k + 1];
        float scale = n / (1.f + n) * rsqrtf(n + 1e-9f);
        float capv = acc * scale;

        if (it == 2) {
            out_cap[((size_t)b * NI_ + k) * D_ + d] = capv;
        } else {
            sh_cap[tid] = capv;
            __syncthreads();
            // delta[k,s] = hat[k,s,:]·cap[k,:];  cw += delta
            for (int t = tid; t < NI_ * S_; t += 256) {
                int kk = t / S_, ss = t - kk * S_;
                const float* hp = &sh_hat[(kk * S_ + ss) * SP];
                const float* cp = &sh_cap[kk * D_];
                float a = 0.f;
                #pragma unroll 8
                for (int d2 = 0; d2 < D_; d2++) a += hp[d2] * cp[d2];
                sh_cw[t] += a;
            }
            __syncthreads();
        }
    }
}

// ============================================================
extern "C" void kernel_launch(void* const* d_in, const int* in_sizes, int n_in,
                              void* d_out, int out_size) {
    const int*   uid     = (const int*)d_in[0];
    const int*   age     = (const int*)d_in[1];
    const int*   gender  = (const int*)d_in[2];
    const int*   occup   = (const int*)d_in[3];
    const int*   mid_his = (const int*)d_in[4];
    const float* mask    = (const float*)d_in[5];
    const float* uet     = (const float*)d_in[6];
    const float* aget    = (const float*)d_in[7];
    const float* gent    = (const float*)d_in[8];
    const float* occt    = (const float*)d_in[9];
    const float* mid_emb = (const float*)d_in[10];
    const float* wcap    = (const float*)d_in[11];

    float* out     = (float*)d_out;
    float* out_cap = out;                                  // (B,NI,D)
    float* out_adj = out + (size_t)B_ * NI_ * D_;          // (B,S,S)

    cudaFuncSetAttribute(adj_kernel,   cudaFuncAttributeMaxDynamicSharedMemorySize, ADJ_SMEM);
    cudaFuncSetAttribute(hat_kernel,   cudaFuncAttributeMaxDynamicSharedMemorySize, HAT_SMEM);
    cudaFuncSetAttribute(route_kernel, cudaFuncAttributeMaxDynamicSharedMemorySize, RT_SMEM);

    up_kernel<<<(B_ * D_ + 255) / 256, 256>>>(uid, age, gender, occup, uet, aget, gent, occt);
    item_kernel<<<(B_ * S_ * (D_ / 4) + 255) / 256, 256>>>(mid_his, mask, mid_emb);
    adj_kernel<<<B_, 256, ADJ_SMEM>>>(mask, out_adj);
    hat_kernel<<<dim3(S_, B_ / 64), 256, HAT_SMEM>>>(wcap);
    route_kernel<<<B_, 256, RT_SMEM>>>(mask, out_cap);
}

// round 3
// speedup vs baseline: 1.2415x; 1.2415x over previous
#include <cuda_runtime.h>
#include <cstdint>
#include <cstddef>

// Problem constants
#define B_   1024
#define S_   200
#define D_   64
#define NI_  4
#define SP   66          // route-kernel padded stride
#define JPAD 224         // padded j extent for adj (7 * 32)

// Strides (words)
#define WT_STR  258      // hat: wT[d][e]    (even: 8B-aligned ld2; mod32=2 -> 2-way wr conflict)
#define IT_STR  65       // hat: it[r][d]
#define AJT_STR 226      // adj: itemT[d][j] (even, mod32=2)
#define HUT_STR 202      // adj: huT[d][i]   (even, mod32=10 -> 2-way)

// Scratch (device globals: allocation-free rule)
__device__ float g_up[B_ * D_];                               // user profile      0.25 MB
__device__ float g_item[(size_t)B_ * S_ * D_];                // item_his          52.4 MB
__device__ float g_hat[(size_t)B_ * NI_ * S_ * D_];           // hat (B,NI,S,D)    209.7 MB

// ---- packed f32x2 helpers (sm_100+) ----
typedef unsigned long long ull;
__device__ __forceinline__ ull ld2(const float* p) {
    return *reinterpret_cast<const ull*>(p);
}
__device__ __forceinline__ void fma2(ull& d, ull a, ull b) {
    asm("fma.rn.f32x2 %0, %1, %2, %3;" : "=l"(d) : "l"(a), "l"(b), "l"(d));
}
__device__ __forceinline__ ull dup2(float v) {
    ull r;
    asm("mov.b64 %0, {%1, %1};" : "=l"(r) : "f"(v));
    return r;
}
__device__ __forceinline__ void unpack2(ull v, float& lo, float& hi) {
    asm("mov.b64 {%0, %1}, %2;" : "=f"(lo), "=f"(hi) : "l"(v));
}

// ============================================================
// K1a: user_profile = 0.25*(U[uid] + G[gender] + A[age] + O[occup])
// ============================================================
__global__ void up_kernel(const int* __restrict__ uid, const int* __restrict__ age,
                          const int* __restrict__ gender, const int* __restrict__ occup,
                          const float* __restrict__ uet, const float* __restrict__ aget,
                          const float* __restrict__ gent, const float* __restrict__ occt) {
    int t = blockIdx.x * blockDim.x + threadIdx.x;
    if (t >= B_ * D_) return;
    int b = t >> 6, d = t & 63;
    float v = uet[(size_t)uid[b] * D_ + d]
            + gent[(size_t)gender[b] * D_ + d]
            + aget[(size_t)age[b] * D_ + d]
            + occt[(size_t)occup[b] * D_ + d];
    g_up[t] = 0.25f * v;
}

// ============================================================
// K1b: item_his[b,s,:] = mid_emb[mid_his[b,s],:] * mask[b,s]   (float4)
// ============================================================
__global__ void item_kernel(const int* __restrict__ mid_his, const float* __restrict__ mask,
                            const float* __restrict__ mid_emb) {
    int i = blockIdx.x * blockDim.x + threadIdx.x;
    if (i >= B_ * S_ * (D_ / 4)) return;
    int bs = i >> 4;
    int d4 = i & 15;
    float m = mask[bs];
    int idx = mid_his[bs];
    float4 v = reinterpret_cast<const float4*>(mid_emb)[(size_t)idx * 16 + d4];
    v.x *= m; v.y *= m; v.z *= m; v.w *= m;
    reinterpret_cast<float4*>(g_item)[i] = v;
}

// ============================================================
// K2 v2: adj[b,i,j] = sigmoid(hu[b,i]·item[b,j]) * mask_i * mask_j
// one block per b. i-PAIRS packed in f32x2 (acc = (i, i+1) outputs).
// smem: itemT[d][j] (b-side, unique per lane), huT[d][i] (a-side, bcast ld2).
// 2 CTAs/SM: smem 110.7 KB, regs capped at 128.
// ============================================================
#define ADJ_SMEM ((D_ * AJT_STR + D_ * HUT_STR + JPAD + D_) * 4)
__global__ void __launch_bounds__(256, 2)
adj_kernel(const float* __restrict__ mask, float* __restrict__ out_adj) {
    extern __shared__ float sm[];
    float* itemT   = sm;                        // [64][226]
    float* huT     = itemT + D_ * AJT_STR;      // [64][202]
    float* sh_mask = huT + D_ * HUT_STR;        // [224]
    float* sh_up   = sh_mask + JPAD;            // [64]

    int b = blockIdx.x;
    int tid = threadIdx.x;

    if (tid < D_) sh_up[tid] = g_up[b * D_ + tid];
    for (int s = tid; s < JPAD; s += 256)
        sh_mask[s] = (s < S_) ? mask[b * S_ + s] : 0.f;
    __syncthreads();

    // transposed loads: itemT[d][j] = item[b,j,d]; huT[d][i] = item*up
    for (int f = tid; f < JPAD * D_; f += 256) {
        int j = f >> 6, d = f & 63;
        float v = (j < S_) ? g_item[((size_t)b * S_ + j) * D_ + d] : 0.f;
        itemT[d * AJT_STR + j] = v;
        if (j < S_) huT[d * HUT_STR + j] = v * sh_up[d];
    }
    __syncthreads();

    int tx = tid & 31, wid = tid >> 5;

    for (int g = wid; g < 25; g += 8) {          // 25 groups of 8 i-rows (4 pairs)
        int i0 = g * 8;
        ull acc[4][7];
        #pragma unroll
        for (int p = 0; p < 4; p++)
            #pragma unroll
            for (int c = 0; c < 7; c++) acc[p][c] = 0ULL;

        #pragma unroll 4
        for (int d = 0; d < D_; d++) {
            ull a[4], bj[7];
            #pragma unroll
            for (int p = 0; p < 4; p++)
                a[p] = ld2(&huT[d * HUT_STR + i0 + 2 * p]);      // bcast pair (i,i+1)
            #pragma unroll
            for (int c = 0; c < 7; c++)
                bj[c] = dup2(itemT[d * AJT_STR + tx + 32 * c]);  // per-lane j, dup
            #pragma unroll
            for (int p = 0; p < 4; p++)
                #pragma unroll
                for (int c = 0; c < 7; c++) fma2(acc[p][c], a[p], bj[c]);
        }

        #pragma unroll
        for (int p = 0; p < 4; p++) {
            int i = i0 + 2 * p;
            float mi0 = sh_mask[i], mi1 = sh_mask[i + 1];
            #pragma unroll
            for (int c = 0; c < 7; c++) {
                int j = tx + 32 * c;
                if (j < S_) {
                    float lo, hi;
                    unpack2(acc[p][c], lo, hi);
                    float mj = sh_mask[j];
                    out_adj[((size_t)b * S_ + i) * S_ + j]       = mi0 * mj / (1.f + __expf(-lo));
                    out_adj[((size_t)b * S_ + (i + 1)) * S_ + j] = mi1 * mj / (1.f + __expf(-hi));
                }
            }
        }
    }
}

// ============================================================
// K3 v2: hat[b,s,e] = item[b,s,:]·w_capsule[s,e,:]; store (B,NI,S,D)
// block = (s, b-tile 64). e-PAIRS packed in f32x2 (wT[d][e] transposed),
// a-side = broadcast scalar duplicated. 2 CTAs/SM.
// ============================================================
#define HAT_SMEM ((D_ * WT_STR + 64 * IT_STR) * 4)
__global__ void __launch_bounds__(256, 2)
hat_kernel(const float* __restrict__ wcap) {
    extern __shared__ float sm[];
    float* sh_wT = sm;                      // [64 d][258]  (e = 0..255)
    float* sh_it = sm + D_ * WT_STR;        // [64 r][65]

    int s  = blockIdx.x;
    int b0 = blockIdx.y * 64;
    int tid = threadIdx.x;

    const float* wsrc = wcap + (size_t)s * 256 * D_;
    for (int f = tid; f < 256 * D_; f += 256) {
        int e = f >> 6, d = f & 63;
        sh_wT[d * WT_STR + e] = wsrc[f];            // transpose: wT[d][e]
    }
    for (int f = tid; f < 64 * D_; f += 256) {
        int r = f >> 6, d = f & 63;
        sh_it[r * IT_STR + d] = g_item[(((size_t)(b0 + r)) * S_ + s) * D_ + d];
    }
    __syncthreads();

    int tx = tid & 31, ty = tid >> 5;
    ull acc[8][4];
    #pragma unroll
    for (int r = 0; r < 8; r++)
        #pragma unroll
        for (int c = 0; c < 4; c++) acc[r][c] = 0ULL;

    #pragma unroll 4
    for (int d = 0; d < D_; d++) {
        ull ad[8], bv[4];
        #pragma unroll
        for (int r = 0; r < 8; r++)
            ad[r] = dup2(sh_it[(ty * 8 + r) * IT_STR + d]);          // warp-bcast scalar
        #pragma unroll
        for (int c = 0; c < 4; c++)
            bv[c] = ld2(&sh_wT[d * WT_STR + 2 * (tx + 32 * c)]);     // e-pair
        #pragma unroll
        for (int r = 0; r < 8; r++)
            #pragma unroll
            for (int c = 0; c < 4; c++) fma2(acc[r][c], ad[r], bv[c]);
    }

    #pragma unroll
    for (int r = 0; r < 8; r++) {
        int b = b0 + ty * 8 + r;
        #pragma unroll
        for (int c = 0; c < 4; c++) {
            int e = 2 * (tx + 32 * c);
            int k = e >> 6, d = e & 63;
            float lo, hi;
            unpack2(acc[r][c], lo, hi);
            float2 v2 = make_float2(lo, hi);
            *reinterpret_cast<float2*>(&g_hat[(((size_t)b * NI_ + k) * S_ + s) * D_ + d]) = v2;
        }
    }
}

// ============================================================
// K4: dynamic routing (3 iters), block per b, hat[b] cached in smem
// ============================================================
#define RT_HAT  (NI_ * S_ * SP)                 // 52800 floats
#define RT_SMEM ((RT_HAT + 800 + 800 + S_ + 256 + 8) * 4)
__global__ void __launch_bounds__(256, 1)
route_kernel(const float* __restrict__ mask, float* __restrict__ out_cap) {
    extern __shared__ float sm[];
    float* sh_hat  = sm;                    // [NI][S][SP]
    float* sh_cw   = sh_hat + RT_HAT;       // [NI][S]
    float* sh_sw   = sh_cw + 800;           // [NI][S]
    float* sh_mask = sh_sw + 800;           // [S]
    float* sh_cap  = sh_mask + S_;          // [NI][D]
    float* sh_red  = sh_cap + 256;          // [8]

    int b = blockIdx.x, tid = threadIdx.x;
    const float* src = g_hat + (size_t)b * NI_ * S_ * D_;

    for (int f = tid; f < NI_ * S_ * (D_ / 4); f += 256) {
        int flat = f * 4;
        int ks = flat >> 6;
        int d  = flat & 63;
        float4 v = reinterpret_cast<const float4*>(src)[f];
        float* dst = &sh_hat[ks * SP + d];
        dst[0] = v.x; dst[1] = v.y; dst[2] = v.z; dst[3] = v.w;
    }
    for (int f = tid; f < 800; f += 256) sh_cw[f] = 0.f;
    if (tid < S_) sh_mask[tid] = mask[b * S_ + tid];
    __syncthreads();

    int k = tid >> 6, d = tid & 63;
    int lane = tid & 31, wid = tid >> 5;

    for (int it = 0; it < 3; it++) {
        if (tid < S_) {
            float c0 = sh_cw[tid], c1 = sh_cw[200 + tid],
                  c2 = sh_cw[400 + tid], c3 = sh_cw[600 + tid];
            float m = fmaxf(fmaxf(c0, c1), fmaxf(c2, c3));
            float e0 = __expf(c0 - m), e1 = __expf(c1 - m),
                  e2 = __expf(c2 - m), e3 = __expf(c3 - m);
            float inv = 1.f / (e0 + e1 + e2 + e3);
            float z = (sh_mask[tid] == 0.f) ? 0.f : inv;
            sh_sw[tid]       = e0 * z;
            sh_sw[200 + tid] = e1 * z;
            sh_sw[400 + tid] = e2 * z;
            sh_sw[600 + tid] = e3 * z;
        }
        __syncthreads();

        float acc = 0.f;
        {
            const float* hb  = &sh_hat[k * S_ * SP + d];
            const float* swb = &sh_sw[k * S_];
            #pragma unroll 4
            for (int s2 = 0; s2 < S_; s2++) acc += swb[s2] * hb[s2 * SP];
        }
        float nsq = acc * acc;
        #pragma unroll
        for (int off = 16; off > 0; off >>= 1)
            nsq += __shfl_xor_sync(0xffffffffu, nsq, off);
        if (lane == 0) sh_red[wid] = nsq;
        __syncthreads();
        float n = sh_red[2 * k] + sh_red[2 * k + 1];
        float scale = n / (1.f + n) * rsqrtf(n + 1e-9f);
        float capv = acc * scale;

        if (it == 2) {
            out_cap[((size_t)b * NI_ + k) * D_ + d] = capv;
        } else {
            sh_cap[tid] = capv;
            __syncthreads();
            for (int t = tid; t < NI_ * S_; t += 256) {
                int kk = t / S_, ss = t - kk * S_;
                const float* hp = &sh_hat[(kk * S_ + ss) * SP];
                const float* cp = &sh_cap[kk * D_];
                float a = 0.f;
                #pragma unroll 8
                for (int d2 = 0; d2 < D_; d2++) a += hp[d2] * cp[d2];
                sh_cw[t] += a;
            }
            __syncthreads();
        }
    }
}

// ============================================================
extern "C" void kernel_launch(void* const* d_in, const int* in_sizes, int n_in,
                              void* d_out, int out_size) {
    const int*   uid     = (const int*)d_in[0];
    const int*   age     = (const int*)d_in[1];
    const int*   gender  = (const int*)d_in[2];
    const int*   occup   = (const int*)d_in[3];
    const int*   mid_his = (const int*)d_in[4];
    const float* mask    = (const float*)d_in[5];
    const float* uet     = (const float*)d_in[6];
    const float* aget    = (const float*)d_in[7];
    const float* gent    = (const float*)d_in[8];
    const float* occt    = (const float*)d_in[9];
    const float* mid_emb = (const float*)d_in[10];
    const float* wcap    = (const float*)d_in[11];

    float* out     = (float*)d_out;
    float* out_cap = out;                                  // (B,NI,D)
    float* out_adj = out + (size_t)B_ * NI_ * D_;          // (B,S,S)

    cudaFuncSetAttribute(adj_kernel,   cudaFuncAttributeMaxDynamicSharedMemorySize, ADJ_SMEM);
    cudaFuncSetAttribute(hat_kernel,   cudaFuncAttributeMaxDynamicSharedMemorySize, HAT_SMEM);
    cudaFuncSetAttribute(route_kernel, cudaFuncAttributeMaxDynamicSharedMemorySize, RT_SMEM);

    up_kernel<<<(B_ * D_ + 255) / 256, 256>>>(uid, age, gender, occup, uet, aget, gent, occt);
    item_kernel<<<(B_ * S_ * (D_ / 4) + 255) / 256, 256>>>(mid_his, mask, mid_emb);
    adj_kernel<<<B_, 256, ADJ_SMEM>>>(mask, out_adj);
    hat_kernel<<<dim3(S_, B_ / 64), 256, HAT_SMEM>>>(wcap);
    route_kernel<<<B_, 256, RT_SMEM>>>(mask, out_cap);
}

// round 5
// speedup vs baseline: 1.3041x; 1.0505x over previous
#include <cuda_runtime.h>
#include <cstdint>
#include <cstddef>

// Problem constants
#define B_   1024
#define S_   200
#define D_   64
#define NI_  4
#define SP   66          // route-kernel padded stride
#define JPAD 224         // padded j extent for adj (7 * 32)
#define IPAD 204         // padded i extent for adj (34 * 6)

// Strides (words)
#define WT_STR  130      // hat: wT[d][e_local], e-tile = 128 (+2 pad)
#define IT_STR  65       // hat: it[r][d]
#define AJT_STR 226      // adj: itemT[d][j] (even, mod32=2 -> 2-way wr conflict only)

// Scratch (device globals: allocation-free rule)
__device__ float g_up[B_ * D_];                               // user profile      0.25 MB
__device__ float g_item[(size_t)B_ * S_ * D_];                // item_his          52.4 MB
__device__ float g_hat[(size_t)B_ * NI_ * S_ * D_];           // hat (B,NI,S,D)    209.7 MB

// ---- packed f32x2 helpers (sm_100+) ----
typedef unsigned long long ull;
__device__ __forceinline__ ull ld2(const float* p) {
    return *reinterpret_cast<const ull*>(p);
}
__device__ __forceinline__ void fma2(ull& d, ull a, ull b) {
    asm("fma.rn.f32x2 %0, %1, %2, %3;" : "=l"(d) : "l"(a), "l"(b), "l"(d));
}
__device__ __forceinline__ ull mul2(ull a, ull b) {
    ull r;
    asm("mul.rn.f32x2 %0, %1, %2;" : "=l"(r) : "l"(a), "l"(b));
    return r;
}
__device__ __forceinline__ ull dup2(float v) {
    ull r;
    asm("mov.b64 %0, {%1, %1};" : "=l"(r) : "f"(v));
    return r;
}
__device__ __forceinline__ void unpack2(ull v, float& lo, float& hi) {
    asm("mov.b64 {%0, %1}, %2;" : "=f"(lo), "=f"(hi) : "l"(v));
}

// ============================================================
// K1a: user_profile = 0.25*(U[uid] + G[gender] + A[age] + O[occup])
// ============================================================
__global__ void up_kernel(const int* __restrict__ uid, const int* __restrict__ age,
                          const int* __restrict__ gender, const int* __restrict__ occup,
                          const float* __restrict__ uet, const float* __restrict__ aget,
                          const float* __restrict__ gent, const float* __restrict__ occt) {
    int t = blockIdx.x * blockDim.x + threadIdx.x;
    if (t >= B_ * D_) return;
    int b = t >> 6, d = t & 63;
    float v = uet[(size_t)uid[b] * D_ + d]
            + gent[(size_t)gender[b] * D_ + d]
            + aget[(size_t)age[b] * D_ + d]
            + occt[(size_t)occup[b] * D_ + d];
    g_up[t] = 0.25f * v;
}

// ============================================================
// K1b: item_his[b,s,:] = mid_emb[mid_his[b,s],:] * mask[b,s]   (float4)
// ============================================================
__global__ void item_kernel(const int* __restrict__ mid_his, const float* __restrict__ mask,
                            const float* __restrict__ mid_emb) {
    int i = blockIdx.x * blockDim.x + threadIdx.x;
    if (i >= B_ * S_ * (D_ / 4)) return;
    int bs = i >> 4;
    int d4 = i & 15;
    float m = mask[bs];
    int idx = mid_his[bs];
    float4 v = reinterpret_cast<const float4*>(mid_emb)[(size_t)idx * 16 + d4];
    v.x *= m; v.y *= m; v.z *= m; v.w *= m;
    reinterpret_cast<float4*>(g_item)[i] = v;
}

// ============================================================
// K2 v3: adj[b,i,j] = sigmoid(sum_d item_i*up*item_j) * mi * mj
// one block per b. huT removed: up folded into a-side (1 mul2/pair/d).
// i-tile per warp-group = 6 rows (3 pairs) -> acc 42 regs -> 3 CTAs/SM.
// ============================================================
#define ADJ_SMEM ((D_ * AJT_STR + JPAD + D_) * 4)
__global__ void __launch_bounds__(256, 3)
adj_kernel(const float* __restrict__ mask, float* __restrict__ out_adj) {
    extern __shared__ float sm[];
    float* itemT   = sm;                        // [64][226]  (j zero-padded to 224)
    float* sh_mask = itemT + D_ * AJT_STR;      // [224]
    float* sh_up   = sh_mask + JPAD;            // [64]

    int b = blockIdx.x;
    int tid = threadIdx.x;

    if (tid < D_) sh_up[tid] = g_up[b * D_ + tid];
    for (int s = tid; s < JPAD; s += 256)
        sh_mask[s] = (s < S_) ? mask[b * S_ + s] : 0.f;

    for (int f = tid; f < JPAD * D_; f += 256) {
        int j = f >> 6, d = f & 63;
        float v = (j < S_) ? g_item[((size_t)b * S_ + j) * D_ + d] : 0.f;
        itemT[d * AJT_STR + j] = v;
    }
    __syncthreads();

    int tx = tid & 31, wid = tid >> 5;

    for (int g = wid; g < IPAD / 6; g += 8) {    // 34 groups of 6 i-rows (3 pairs)
        int i0 = g * 6;
        ull acc[3][7];
        #pragma unroll
        for (int p = 0; p < 3; p++)
            #pragma unroll
            for (int c = 0; c < 7; c++) acc[p][c] = 0ULL;

        #pragma unroll 2
        for (int d = 0; d < D_; d++) {
            const float* row = &itemT[d * AJT_STR];
            ull up2 = dup2(sh_up[d]);
            ull a[3], bj[7];
            #pragma unroll
            for (int p = 0; p < 3; p++)
                a[p] = mul2(ld2(&row[i0 + 2 * p]), up2);     // (i,i+1) pair * up[d]
            #pragma unroll
            for (int c = 0; c < 7; c++)
                bj[c] = dup2(row[tx + 32 * c]);              // per-lane j, dup
            #pragma unroll
            for (int p = 0; p < 3; p++)
                #pragma unroll
                for (int c = 0; c < 7; c++) fma2(acc[p][c], a[p], bj[c]);
        }

        #pragma unroll
        for (int p = 0; p < 3; p++) {
            int i = i0 + 2 * p;
            if (i >= S_) break;
            float mi0 = sh_mask[i], mi1 = sh_mask[i + 1];
            bool ok1 = (i + 1 < S_);
            #pragma unroll
            for (int c = 0; c < 7; c++) {
                int j = tx + 32 * c;
                if (j < S_) {
                    float lo, hi;
                    unpack2(acc[p][c], lo, hi);
                    float mj = sh_mask[j];
                    out_adj[((size_t)b * S_ + i) * S_ + j] = mi0 * mj / (1.f + __expf(-lo));
                    if (ok1)
                        out_adj[((size_t)b * S_ + (i + 1)) * S_ + j] = mi1 * mj / (1.f + __expf(-hi));
                }
            }
        }
    }
}

// ============================================================
// K3 v3: hat[b,s,e] = item[b,s,:]·w_capsule[s,e,:]; store (B,NI,S,D)
// block = (s, b-tile 64, e-half 128). e-PAIRS in f32x2.
// smem 49.9 KB, regs <= 85 -> 3 CTAs/SM (24 warps).
// ============================================================
#define HAT_SMEM ((D_ * WT_STR + 64 * IT_STR) * 4)
__global__ void __launch_bounds__(256, 3)
hat_kernel(const float* __restrict__ wcap) {
    extern __shared__ float sm[];
    float* sh_wT = sm;                      // [64 d][130]  (e_local = 0..127)
    float* sh_it = sm + D_ * WT_STR;        // [64 r][65]

    int s  = blockIdx.x;
    int b0 = blockIdx.y * 64;
    int e0 = blockIdx.z * 128;
    int tid = threadIdx.x;

    const float* wsrc = wcap + ((size_t)s * 256 + e0) * D_;
    for (int f = tid; f < 128 * D_; f += 256) {
        int el = f >> 6, d = f & 63;
        sh_wT[d * WT_STR + el] = wsrc[f];           // transpose: wT[d][e_local]
    }
    for (int f = tid; f < 64 * D_; f += 256) {
        int r = f >> 6, d = f & 63;
        sh_it[r * IT_STR + d] = g_item[(((size_t)(b0 + r)) * S_ + s) * D_ + d];
    }
    __syncthreads();

    int tx = tid & 31, ty = tid >> 5;
    ull acc[8][2];
    #pragma unroll
    for (int r = 0; r < 8; r++)
        #pragma unroll
        for (int c = 0; c < 2; c++) acc[r][c] = 0ULL;

    #pragma unroll 4
    for (int d = 0; d < D_; d++) {
        ull ad[8], bv[2];
        #pragma unroll
        for (int r = 0; r < 8; r++)
            ad[r] = dup2(sh_it[(ty * 8 + r) * IT_STR + d]);      // warp-bcast scalar
        #pragma unroll
        for (int c = 0; c < 2; c++)
            bv[c] = ld2(&sh_wT[d * WT_STR + 2 * (tx + 32 * c)]); // e-pair
        #pragma unroll
        for (int r = 0; r < 8; r++)
            #pragma unroll
            for (int c = 0; c < 2; c++) fma2(acc[r][c], ad[r], bv[c]);
    }

    #pragma unroll
    for (int r = 0; r < 8; r++) {
        int b = b0 + ty * 8 + r;
        #pragma unroll
        for (int c = 0; c < 2; c++) {
            int e = e0 + 2 * (tx + 32 * c);
            int k = e >> 6, d = e & 63;
            float lo, hi;
            unpack2(acc[r][c], lo, hi);
            float2 v2 = make_float2(lo, hi);
            *reinterpret_cast<float2*>(&g_hat[(((size_t)b * NI_ + k) * S_ + s) * D_ + d]) = v2;
        }
    }
}

// ============================================================
// K4: dynamic routing (3 iters), block per b, hat[b] cached in smem
// ============================================================
#define RT_HAT  (NI_ * S_ * SP)                 // 52800 floats
#define RT_SMEM ((RT_HAT + 800 + 800 + S_ + 256 + 8) * 4)
__global__ void __launch_bounds__(256, 1)
route_kernel(const float* __restrict__ mask, float* __restrict__ out_cap) {
    extern __shared__ float sm[];
    float* sh_hat  = sm;                    // [NI][S][SP]
    float* sh_cw   = sh_hat + RT_HAT;       // [NI][S]
    float* sh_sw   = sh_cw + 800;           // [NI][S]
    float* sh_mask = sh_sw + 800;           // [S]
    float* sh_cap  = sh_mask + S_;          // [NI][D]
    float* sh_red  = sh_cap + 256;          // [8]

    int b = blockIdx.x, tid = threadIdx.x;
    const float* src = g_hat + (size_t)b * NI_ * S_ * D_;

    for (int f = tid; f < NI_ * S_ * (D_ / 4); f += 256) {
        int flat = f * 4;
        int ks = flat >> 6;
        int d  = flat & 63;
        float4 v = reinterpret_cast<const float4*>(src)[f];
        float* dst = &sh_hat[ks * SP + d];
        dst[0] = v.x; dst[1] = v.y; dst[2] = v.z; dst[3] = v.w;
    }
    for (int f = tid; f < 800; f += 256) sh_cw[f] = 0.f;
    if (tid < S_) sh_mask[tid] = mask[b * S_ + tid];
    __syncthreads();

    int k = tid >> 6, d = tid & 63;
    int lane = tid & 31, wid = tid >> 5;

    for (int it = 0; it < 3; it++) {
        if (tid < S_) {
            float c0 = sh_cw[tid], c1 = sh_cw[200 + tid],
                  c2 = sh_cw[400 + tid], c3 = sh_cw[600 + tid];
            float m = fmaxf(fmaxf(c0, c1), fmaxf(c2, c3));
            float e0 = __expf(c0 - m), e1 = __expf(c1 - m),
                  e2 = __expf(c2 - m), e3 = __expf(c3 - m);
            float inv = 1.f / (e0 + e1 + e2 + e3);
            float z = (sh_mask[tid] == 0.f) ? 0.f : inv;
            sh_sw[tid]       = e0 * z;
            sh_sw[200 + tid] = e1 * z;
            sh_sw[400 + tid] = e2 * z;
            sh_sw[600 + tid] = e3 * z;
        }
        __syncthreads();

        float acc = 0.f;
        {
            const float* hb  = &sh_hat[k * S_ * SP + d];
            const float* swb = &sh_sw[k * S_];
            #pragma unroll 4
            for (int s2 = 0; s2 < S_; s2++) acc += swb[s2] * hb[s2 * SP];
        }
        float nsq = acc * acc;
        #pragma unroll
        for (int off = 16; off > 0; off >>= 1)
            nsq += __shfl_xor_sync(0xffffffffu, nsq, off);
        if (lane == 0) sh_red[wid] = nsq;
        __syncthreads();
        float n = sh_red[2 * k] + sh_red[2 * k + 1];
        float scale = n / (1.f + n) * rsqrtf(n + 1e-9f);
        float capv = acc * scale;

        if (it == 2) {
            out_cap[((size_t)b * NI_ + k) * D_ + d] = capv;
        } else {
            sh_cap[tid] = capv;
            __syncthreads();
            for (int t = tid; t < NI_ * S_; t += 256) {
                int kk = t / S_, ss = t - kk * S_;
                const float* hp = &sh_hat[(kk * S_ + ss) * SP];
                const float* cp = &sh_cap[kk * D_];
                float a = 0.f;
                #pragma unroll 8
                for (int d2 = 0; d2 < D_; d2++) a += hp[d2] * cp[d2];
                sh_cw[t] += a;
            }
            __syncthreads();
        }
    }
}

// ============================================================
extern "C" void kernel_launch(void* const* d_in, const int* in_sizes, int n_in,
                              void* d_out, int out_size) {
    const int*   uid     = (const int*)d_in[0];
    const int*   age     = (const int*)d_in[1];
    const int*   gender  = (const int*)d_in[2];
    const int*   occup   = (const int*)d_in[3];
    const int*   mid_his = (const int*)d_in[4];
    const float* mask    = (const float*)d_in[5];
    const float* uet     = (const float*)d_in[6];
    const float* aget    = (const float*)d_in[7];
    const float* gent    = (const float*)d_in[8];
    const float* occt    = (const float*)d_in[9];
    const float* mid_emb = (const float*)d_in[10];
    const float* wcap    = (const float*)d_in[11];

    float* out     = (float*)d_out;
    float* out_cap = out;                                  // (B,NI,D)
    float* out_adj = out + (size_t)B_ * NI_ * D_;          // (B,S,S)

    cudaFuncSetAttribute(adj_kernel,   cudaFuncAttributeMaxDynamicSharedMemorySize, ADJ_SMEM);
    cudaFuncSetAttribute(hat_kernel,   cudaFuncAttributeMaxDynamicSharedMemorySize, HAT_SMEM);
    cudaFuncSetAttribute(route_kernel, cudaFuncAttributeMaxDynamicSharedMemorySize, RT_SMEM);

    up_kernel<<<(B_ * D_ + 255) / 256, 256>>>(uid, age, gender, occup, uet, aget, gent, occt);
    item_kernel<<<(B_ * S_ * (D_ / 4) + 255) / 256, 256>>>(mid_his, mask, mid_emb);
    adj_kernel<<<B_, 256, ADJ_SMEM>>>(mask, out_adj);
    hat_kernel<<<dim3(S_, B_ / 64, 2), 256, HAT_SMEM>>>(wcap);
    route_kernel<<<B_, 256, RT_SMEM>>>(mask, out_cap);
}